// round 3
// baseline (speedup 1.0000x reference)
#include <cuda_runtime.h>
#include <cstddef>

typedef unsigned long long ull;

#define Bx 8
#define Nx 8192
#define Cx 128
#define Hx 8
#define Gx 32
#define HD 512
#define LN_EPS 1e-5f

// ---------------------------------------------------------------------------
// Scratch (device globals)
// ---------------------------------------------------------------------------
__device__ __align__(16) float g_Ypart[Bx][32][Gx * Cx];   // 4 MB
__device__ __align__(16) float g_Y[Bx][Gx * Cx];
__device__ __align__(16) float g_Spart[32][Gx];
__device__ __align__(16) float g_M[HD * Cx];               // M[(h,i)][m] = sum_o mlp[i,o] Wout[h*64+o,m]
__device__ __align__(16) float g_lngT[64 * 32];            // ln_g transposed [c][g]
__device__ __align__(16) float g_lnbT[64 * 32];
__device__ __align__(16) float g_spec[Bx][Hx][64 * 32];    // raw spec [c][g]
__device__ __align__(16) float g_stat[Bx][Hx][2][2];       // per c-half {sum, sumsq}
__device__ __align__(16) float g_Zp[Bx][Hx][Gx * Cx];
__device__ __align__(16) float g_Zs[Bx][Gx * Cx];

// ---------------------------------------------------------------------------
// Helpers
// ---------------------------------------------------------------------------
__device__ __forceinline__ void fma2(ull& d, ull a, ull b) {
    asm("fma.rn.f32x2 %0, %1, %2, %0;" : "+l"(d) : "l"(a), "l"(b));
}
__device__ __forceinline__ ull dup2(float v) {
    ull r; asm("mov.b64 %0, {%1, %1};" : "=l"(r) : "f"(v)); return r;
}
__device__ __forceinline__ ull pack2(float a, float b) {
    ull r; asm("mov.b64 %0, {%1, %2};" : "=l"(r) : "f"(a), "f"(b)); return r;
}
__device__ __forceinline__ float2 unpk(ull v) {
    float2 f; asm("mov.b64 {%0, %1}, %2;" : "=f"(f.x), "=f"(f.y) : "l"(v)); return f;
}
__device__ __forceinline__ unsigned smem_u32(const void* p) {
    return (unsigned)__cvta_generic_to_shared(p);
}
__device__ __forceinline__ void cp16(unsigned dst, const void* src) {
    asm volatile("cp.async.cg.shared.global [%0], [%1], 16;" :: "r"(dst), "l"(src));
}
#define CP_COMMIT() asm volatile("cp.async.commit_group;")
#define CP_WAIT0()  asm volatile("cp.async.wait_group 0;")

// ---------------------------------------------------------------------------
// k_front: blocks 0..127 stage1 encode; 128..135 M precompute; 136 ln transpose
// stage1: block (b, ch of 16): 512 rows, 2 row-groups of 256 rows.
//   thread (rg, gt, kt): acc 4g x 8k (k split kt*4 / kt*4+64 -> conflict-free)
// ---------------------------------------------------------------------------
__global__ __launch_bounds__(256) void k_front(const float* __restrict__ x,
                                               const float* __restrict__ inv_in,
                                               const float* __restrict__ mlp_w,
                                               const float* __restrict__ W_out,
                                               const float* __restrict__ ln_g,
                                               const float* __restrict__ ln_b)
{
    extern __shared__ __align__(16) float dsm[];
    const int blk = blockIdx.x;
    const int t = threadIdx.x;

    if (blk < 128) {
        float* sx = dsm;                 // [2][32*128]
        float* sv = dsm + 2 * 4096;      // [2][32*32]
        const int b = blk >> 4, ch = blk & 15;
        const int rg = t >> 7;
        const int t128 = t & 127;
        const int kt = t128 & 15, gt = t128 >> 4;
        const int k0a = kt * 4, k0b = kt * 4 + 64;
        const int g0 = gt * 4;

        const float* xb = x + (size_t)b * Nx * Cx + (size_t)ch * 512 * Cx;
        const float* vb = inv_in + (size_t)ch * 512 * Gx;

        ull acc[4][4];
#pragma unroll
        for (int j = 0; j < 4; j++)
#pragma unroll
            for (int q = 0; q < 4; q++) acc[j][q] = 0ull;

        // stage loader: 32 rows (16 for each row-group)
        auto ldstage = [&](int s, int buf) {
            unsigned bxu = smem_u32(sx + buf * 4096);
            unsigned bvu = smem_u32(sv + buf * 1024);
#pragma unroll
            for (int j = 0; j < 4; j++) {
                const int idx = t + 256 * j;
                const int row = idx >> 5, c4 = idx & 31;
                const int gr = (row < 16) ? (s * 16 + row) : (256 + s * 16 + row - 16);
                cp16(bxu + (unsigned)(row * 128 + c4 * 4) * 4, xb + (size_t)gr * Cx + c4 * 4);
            }
            {
                const int row = t >> 3, gq = t & 7;
                const int gr = (row < 16) ? (s * 16 + row) : (256 + s * 16 + row - 16);
                cp16(bvu + (unsigned)(row * 32 + gq * 4) * 4, vb + (size_t)gr * Gx + gq * 4);
            }
            CP_COMMIT();
        };

        ldstage(0, 0);
        for (int s = 0; s < 16; s++) {
            CP_WAIT0();
            __syncthreads();
            if (s < 15) ldstage(s + 1, (s + 1) & 1);
            const float* bx = sx + (s & 1) * 4096 + (rg * 16) * 128;
            const float* bv = sv + (s & 1) * 1024 + (rg * 16) * 32;
#pragma unroll
            for (int r = 0; r < 16; r++) {
                ulonglong2 xv0 = *(const ulonglong2*)&bx[r * 128 + k0a];
                ulonglong2 xv1 = *(const ulonglong2*)&bx[r * 128 + k0b];
                float4 v4 = *(const float4*)&bv[r * 32 + g0];
                ull d;
                d = dup2(v4.x); fma2(acc[0][0], xv0.x, d); fma2(acc[0][1], xv0.y, d);
                                fma2(acc[0][2], xv1.x, d); fma2(acc[0][3], xv1.y, d);
                d = dup2(v4.y); fma2(acc[1][0], xv0.x, d); fma2(acc[1][1], xv0.y, d);
                                fma2(acc[1][2], xv1.x, d); fma2(acc[1][3], xv1.y, d);
                d = dup2(v4.z); fma2(acc[2][0], xv0.x, d); fma2(acc[2][1], xv0.y, d);
                                fma2(acc[2][2], xv1.x, d); fma2(acc[2][3], xv1.y, d);
                d = dup2(v4.w); fma2(acc[3][0], xv0.x, d); fma2(acc[3][1], xv0.y, d);
                                fma2(acc[3][2], xv1.x, d); fma2(acc[3][3], xv1.y, d);
            }
            __syncthreads();
        }
        float* base = &g_Ypart[b][ch * 2 + rg][0];
#pragma unroll
        for (int j = 0; j < 4; j++) {
            ulonglong2 oa; oa.x = acc[j][0]; oa.y = acc[j][1];
            ulonglong2 ob; ob.x = acc[j][2]; ob.y = acc[j][3];
            *(ulonglong2*)&base[(g0 + j) * 128 + k0a] = oa;
            *(ulonglong2*)&base[(g0 + j) * 128 + k0b] = ob;
        }
    } else if (blk < 136) {
        // M precompute: M_h[i,m] = sum_o mlp_w[i,o] * W_out[h*64+o, m]
        const int h = blk - 128;
        float* sMT = dsm;            // [o][i] 64x64
        float* sWo = dsm + 4096;     // [o][m] 64x128
#pragma unroll
        for (int j = 0; j < 16; j++) {
            const int idx = t + 256 * j;
            const int i = idx >> 6, o = idx & 63;
            sMT[o * 64 + i] = mlp_w[idx];
        }
#pragma unroll
        for (int j = 0; j < 32; j++) {
            const int idx = t + 256 * j;
            sWo[idx] = W_out[h * 64 * Cx + idx];
        }
        __syncthreads();
        const int i0 = 8 * (t >> 5), m0 = 4 * (t & 31);
        ull acc[8][2];
#pragma unroll
        for (int j = 0; j < 8; j++) { acc[j][0] = 0ull; acc[j][1] = 0ull; }
        for (int o = 0; o < 64; o++) {
            ulonglong2 w = *(const ulonglong2*)&sWo[o * 128 + m0];
            float4 a0 = *(const float4*)&sMT[o * 64 + i0];
            float4 a1 = *(const float4*)&sMT[o * 64 + i0 + 4];
            ull d;
            d = dup2(a0.x); fma2(acc[0][0], w.x, d); fma2(acc[0][1], w.y, d);
            d = dup2(a0.y); fma2(acc[1][0], w.x, d); fma2(acc[1][1], w.y, d);
            d = dup2(a0.z); fma2(acc[2][0], w.x, d); fma2(acc[2][1], w.y, d);
            d = dup2(a0.w); fma2(acc[3][0], w.x, d); fma2(acc[3][1], w.y, d);
            d = dup2(a1.x); fma2(acc[4][0], w.x, d); fma2(acc[4][1], w.y, d);
            d = dup2(a1.y); fma2(acc[5][0], w.x, d); fma2(acc[5][1], w.y, d);
            d = dup2(a1.z); fma2(acc[6][0], w.x, d); fma2(acc[6][1], w.y, d);
            d = dup2(a1.w); fma2(acc[7][0], w.x, d); fma2(acc[7][1], w.y, d);
        }
#pragma unroll
        for (int j = 0; j < 8; j++) {
            ulonglong2 o2; o2.x = acc[j][0]; o2.y = acc[j][1];
            *(ulonglong2*)&g_M[(h * 64 + i0 + j) * Cx + m0] = o2;
        }
    } else {
        // ln transpose
#pragma unroll
        for (int j = 0; j < 8; j++) {
            const int idx = t + 256 * j;
            const int g = idx >> 6, c = idx & 63;
            g_lngT[c * 32 + g] = ln_g[idx];
            g_lnbT[c * 32 + g] = ln_b[idx];
        }
    }
}

// ---------------------------------------------------------------------------
// k_mid1: blocks 0..31 reduce Y partials; 32..63 Spart column sums of inv_in
// ---------------------------------------------------------------------------
__global__ __launch_bounds__(256) void k_mid1(const float* __restrict__ inv_in)
{
    const int blk = blockIdx.x, t = threadIdx.x;
    if (blk < 32) {
        const int b = blk >> 2, q = blk & 3;
        const int id = q * 256 + t;         // float4 index, 1024 per b
        float4 a = make_float4(0.f, 0.f, 0.f, 0.f);
#pragma unroll 8
        for (int p = 0; p < 32; p++) {
            float4 v = ((const float4*)g_Ypart[b][p])[id];
            a.x += v.x; a.y += v.y; a.z += v.z; a.w += v.w;
        }
        ((float4*)g_Y[b])[id] = a;
    } else {
        const int ch = blk - 32;
        const int g = t & 31, r = t >> 5;
        const float* vb = inv_in + (size_t)ch * 256 * Gx;
        float a = 0.f;
#pragma unroll 8
        for (int i = 0; i < 32; i++)
            a += vb[(r + 8 * i) * Gx + g];
        __shared__ float sh[256];
        sh[t] = a;
        __syncthreads();
        if (t < 32) {
            float s = 0.f;
#pragma unroll
            for (int rr = 0; rr < 8; rr++) s += sh[rr * 32 + t];
            g_Spart[ch][t] = s;
        }
    }
}

// ---------------------------------------------------------------------------
// k_specA: per (b, h, c-half): spec[g, c] = Y[g,:] @ W_in[:, h*64+c] + S[g]*b_in
// writes raw spec (transposed [c][g]) + LN stat partials. grid 128.
// ---------------------------------------------------------------------------
__global__ __launch_bounds__(256) void k_specA(const float* __restrict__ W_in,
                                               const float* __restrict__ b_in)
{
    __shared__ __align__(16) float sYT[128 * 32];
    __shared__ __align__(16) float sW[128 * 32];
    __shared__ float sRed[16];

    const int blk = blockIdx.x, t = threadIdx.x;
    const int b = blk >> 4, h = (blk >> 1) & 7, chf = blk & 1;

#pragma unroll
    for (int j = 0; j < 16; j++) {
        const int idx = t + 256 * j;
        const int k = idx >> 5, g = idx & 31;
        sYT[idx] = g_Y[b][g * 128 + k];
    }
#pragma unroll
    for (int j = 0; j < 16; j++) {
        const int idx = t + 256 * j;
        const int k = idx >> 5, c = idx & 31;
        sW[idx] = W_in[k * HD + h * 64 + chf * 32 + c];
    }
    __syncthreads();

    const int c0 = 2 * (t & 15), g0 = 2 * (t >> 4);
    ull a0 = 0ull, a1 = 0ull;
#pragma unroll 8
    for (int k = 0; k < 128; k++) {
        float2 y = *(const float2*)&sYT[k * 32 + g0];
        ull w = *(const ull*)&sW[k * 32 + c0];
        fma2(a0, w, dup2(y.x));
        fma2(a1, w, dup2(y.y));
    }
    // bias: + S[g]*b_in[c]
    float S0 = 0.f, S1 = 0.f;
#pragma unroll 8
    for (int p = 0; p < 32; p++) {
        float2 sp = *(const float2*)&g_Spart[p][g0];
        S0 += sp.x; S1 += sp.y;
    }
    ull bp = *(const ull*)&b_in[h * 64 + chf * 32 + c0];
    fma2(a0, bp, dup2(S0));
    fma2(a1, bp, dup2(S1));

    float2 p0 = unpk(a0), p1 = unpk(a1);
    float ls = p0.x + p0.y + p1.x + p1.y;
    float lss = p0.x * p0.x + p0.y * p0.y + p1.x * p1.x + p1.y * p1.y;
#pragma unroll
    for (int o = 16; o; o >>= 1) {
        ls  += __shfl_xor_sync(0xffffffffu, ls,  o);
        lss += __shfl_xor_sync(0xffffffffu, lss, o);
    }
    if ((t & 31) == 0) { sRed[t >> 5] = ls; sRed[8 + (t >> 5)] = lss; }
    __syncthreads();
    if (t == 0) {
        float S = 0.f, SS = 0.f;
#pragma unroll
        for (int w = 0; w < 8; w++) { S += sRed[w]; SS += sRed[8 + w]; }
        g_stat[b][h][chf][0] = S;
        g_stat[b][h][chf][1] = SS;
    }
    // store spec transposed [c][g]
    float* sp = &g_spec[b][h][0];
    const int c = chf * 32 + c0;
    sp[c * 32 + g0]           = p0.x;
    sp[(c + 1) * 32 + g0]     = p0.y;
    sp[c * 32 + g0 + 1]       = p1.x;
    sp[(c + 1) * 32 + g0 + 1] = p1.y;
}

// ---------------------------------------------------------------------------
// k_specZ: per (b, h, m-half): specN = LN(spec)*ln_g + ln_b; Zp = specN @ M_h
// grid 128.
// ---------------------------------------------------------------------------
__global__ __launch_bounds__(256) void k_specZ()
{
    __shared__ __align__(16) float sAT[64 * 32];   // specN [c][g]
    __shared__ __align__(16) float sM[64 * 64];    // M_h [i][m-half]

    const int blk = blockIdx.x, t = threadIdx.x;
    const int b = blk >> 4, h = (blk >> 1) & 7, mh = blk & 1;

    const float s0 = g_stat[b][h][0][0] + g_stat[b][h][1][0];
    const float ss = g_stat[b][h][0][1] + g_stat[b][h][1][1];
    const float mu = s0 * (1.f / 2048.f);
    const float rs = rsqrtf(ss * (1.f / 2048.f) - mu * mu + LN_EPS);

    {
        const int c = t >> 2, g0 = 8 * (t & 3);
        const float* sp = &g_spec[b][h][c * 32 + g0];
        float4 v0 = *(const float4*)sp;
        float4 v1 = *(const float4*)(sp + 4);
        float4 ga = *(const float4*)&g_lngT[c * 32 + g0];
        float4 gb = *(const float4*)&g_lngT[c * 32 + g0 + 4];
        float4 ba = *(const float4*)&g_lnbT[c * 32 + g0];
        float4 bb = *(const float4*)&g_lnbT[c * 32 + g0 + 4];
        float* dst = &sAT[c * 32 + g0];
        float a;
        a = rs * ga.x; dst[0] = v0.x * a + (ba.x - mu * a);
        a = rs * ga.y; dst[1] = v0.y * a + (ba.y - mu * a);
        a = rs * ga.z; dst[2] = v0.z * a + (ba.z - mu * a);
        a = rs * ga.w; dst[3] = v0.w * a + (ba.w - mu * a);
        a = rs * gb.x; dst[4] = v1.x * a + (bb.x - mu * a);
        a = rs * gb.y; dst[5] = v1.y * a + (bb.y - mu * a);
        a = rs * gb.z; dst[6] = v1.z * a + (bb.z - mu * a);
        a = rs * gb.w; dst[7] = v1.w * a + (bb.w - mu * a);
    }
#pragma unroll
    for (int j = 0; j < 16; j++) {
        const int idx = t + 256 * j;
        const int i = idx >> 6, m = idx & 63;
        sM[idx] = g_M[(h * 64 + i) * Cx + mh * 64 + m];
    }
    __syncthreads();

    const int m0 = 2 * (t & 31), g0 = 4 * (t >> 5);
    ull acc[4] = {0ull, 0ull, 0ull, 0ull};
#pragma unroll 8
    for (int i = 0; i < 64; i++) {
        float4 a = *(const float4*)&sAT[i * 32 + g0];
        ull w = *(const ull*)&sM[i * 64 + m0];
        fma2(acc[0], w, dup2(a.x));
        fma2(acc[1], w, dup2(a.y));
        fma2(acc[2], w, dup2(a.z));
        fma2(acc[3], w, dup2(a.w));
    }
#pragma unroll
    for (int j = 0; j < 4; j++)
        *(ull*)&g_Zp[b][h][(g0 + j) * 128 + mh * 64 + m0] = acc[j];
}

// ---------------------------------------------------------------------------
// k_redZ: sum Zp over heads. grid 32.
// ---------------------------------------------------------------------------
__global__ __launch_bounds__(256) void k_redZ()
{
    const int blk = blockIdx.x, t = threadIdx.x;
    const int b = blk >> 2, q = blk & 3;
    const int id = q * 256 + t;
    float4 a = make_float4(0.f, 0.f, 0.f, 0.f);
#pragma unroll
    for (int h = 0; h < Hx; h++) {
        float4 v = ((const float4*)g_Zp[b][h])[id];
        a.x += v.x; a.y += v.y; a.z += v.z; a.w += v.w;
    }
    ((float4*)g_Zs[b])[id] = a;
}

// ---------------------------------------------------------------------------
// k_back: out[b,n,m] = b_out[m] + sum_g inv_out0[n,g] * Zs[b,g,m]
// grid 128: (b, ch of 16) x 512 rows. thread: 4 rows x 16 m (m-granules
// {4mt+32q} -> conflict-free LDS). cp.async double-buffered inv rows.
// ---------------------------------------------------------------------------
__global__ __launch_bounds__(256) void k_back(const float* __restrict__ inv_out,
                                              const float* __restrict__ b_out,
                                              float* __restrict__ out)
{
    extern __shared__ __align__(16) float dsm[];
    float* sZ = dsm;               // 4096
    float* sv = dsm + 4096;        // [2][128*32]

    const int blk = blockIdx.x, t = threadIdx.x;
    const int b = blk >> 4, ch = blk & 15;
    const int mt = t & 7, rt = t >> 3;
    const int r0 = 4 * rt;

    const float* vb = inv_out + (size_t)ch * 512 * Gx;

#pragma unroll
    for (int j = 0; j < 4; j++)
        ((float4*)sZ)[t + 256 * j] = ((const float4*)g_Zs[b])[t + 256 * j];

    auto ldpass = [&](int p, int buf) {
        unsigned bvu = smem_u32(sv + buf * 4096);
#pragma unroll
        for (int j = 0; j < 4; j++) {
            const int idx = t + 256 * j;
            const int row = idx >> 3, gq = idx & 7;
            cp16(bvu + (unsigned)(row * 32 + gq * 4) * 4,
                 vb + (size_t)(p * 128 + row) * Gx + gq * 4);
        }
        CP_COMMIT();
    };
    ldpass(0, 0);

    // bias
    ull bias[8];
#pragma unroll
    for (int q = 0; q < 4; q++) {
        float4 bo = *(const float4*)&b_out[4 * mt + 32 * q];
        bias[2 * q]     = pack2(bo.x, bo.y);
        bias[2 * q + 1] = pack2(bo.z, bo.w);
    }

    float* outb = out + (size_t)b * Nx * Cx + (size_t)ch * 512 * Cx;

    for (int p = 0; p < 4; p++) {
        CP_WAIT0();
        __syncthreads();
        if (p < 3) ldpass(p + 1, (p + 1) & 1);
        const float* vsm = sv + (p & 1) * 4096;

        ull acc[4][8];
#pragma unroll
        for (int r = 0; r < 4; r++)
#pragma unroll
            for (int u = 0; u < 8; u++) acc[r][u] = bias[u];

#pragma unroll
        for (int gq = 0; gq < 8; gq++) {
            float vc[4][4];
#pragma unroll
            for (int r = 0; r < 4; r++) {
                float4 v4 = *(const float4*)&vsm[(r0 + r) * 32 + gq * 4];
                vc[r][0] = v4.x; vc[r][1] = v4.y; vc[r][2] = v4.z; vc[r][3] = v4.w;
            }
#pragma unroll
            for (int e = 0; e < 4; e++) {
                const int g = gq * 4 + e;
                ull z[8];
#pragma unroll
                for (int q = 0; q < 4; q++) {
                    ulonglong2 zz = *(const ulonglong2*)&sZ[g * 128 + 4 * mt + 32 * q];
                    z[2 * q] = zz.x; z[2 * q + 1] = zz.y;
                }
#pragma unroll
                for (int r = 0; r < 4; r++) {
                    ull d = dup2(vc[r][e]);
                    fma2(acc[r][0], z[0], d); fma2(acc[r][1], z[1], d);
                    fma2(acc[r][2], z[2], d); fma2(acc[r][3], z[3], d);
                    fma2(acc[r][4], z[4], d); fma2(acc[r][5], z[5], d);
                    fma2(acc[r][6], z[6], d); fma2(acc[r][7], z[7], d);
                }
            }
        }
#pragma unroll
        for (int r = 0; r < 4; r++) {
            float* orow = outb + (size_t)(p * 128 + r0 + r) * Cx;
#pragma unroll
            for (int q = 0; q < 4; q++) {
                ulonglong2 o2; o2.x = acc[r][2 * q]; o2.y = acc[r][2 * q + 1];
                *(ulonglong2*)&orow[4 * mt + 32 * q] = o2;
            }
        }
        __syncthreads();
    }
}

// ---------------------------------------------------------------------------
// Launch. Inputs: x, W_in, b_in, mlp_w, ln_g, ln_b, W_out, b_out, inv_in, inv_out
// ---------------------------------------------------------------------------
extern "C" void kernel_launch(void* const* d_in, const int* in_sizes, int n_in,
                              void* d_out, int out_size)
{
    const float* x      = (const float*)d_in[0];
    const float* W_in   = (const float*)d_in[1];
    const float* b_in   = (const float*)d_in[2];
    const float* mlp_w  = (const float*)d_in[3];
    const float* ln_g   = (const float*)d_in[4];
    const float* ln_b   = (const float*)d_in[5];
    const float* W_out  = (const float*)d_in[6];
    const float* b_out  = (const float*)d_in[7];
    const float* inv_in = (const float*)d_in[8];   // head-broadcast: use slice 0
    const float* inv_out= (const float*)d_in[9];
    float* out = (float*)d_out;

    const int front_smem = 49152;
    const int back_smem  = 49152;
    cudaFuncSetAttribute(k_front, cudaFuncAttributeMaxDynamicSharedMemorySize, front_smem);
    cudaFuncSetAttribute(k_back,  cudaFuncAttributeMaxDynamicSharedMemorySize, back_smem);

    k_front<<<137, 256, front_smem>>>(x, inv_in, mlp_w, W_out, ln_g, ln_b);
    k_mid1 <<<64, 256>>>(inv_in);
    k_specA<<<128, 256>>>(W_in, b_in);
    k_specZ<<<128, 256>>>();
    k_redZ <<<32, 256>>>();
    k_back <<<128, 256, back_smem>>>(inv_out, b_out, out);
}